// round 13
// baseline (speedup 1.0000x reference)
#include <cuda_runtime.h>
#include <stdint.h>

// IN:  x (4, 64, 224, 224) fp32
// OUT: (4, 576, 223*223) fp32, plane ck = bc*9 + ki*3 + kj
// out[ck, oh*223+ow] = x[bc, oh+ki-1, ow+kj-1] (0 if OOB)
#define OSP   49729u      // 223*223
#define ISTR  50176u      // 224*224
#define CR    24u         // output rows per chunk
#define SR_N  27u         // staged input rows per chunk (CR + 3)

// Block = (24-row output group, bc). 9 warps = 9 (ki,kj) planes.
// v10 store loop (proven best) + bigger chunk: less read redundancy
// (27/24 vs 11/8), 2560 blocks instead of 7168 (fewer sync boundaries).
__global__ void __launch_bounds__(288, 7) unfold_v13(const float* __restrict__ x,
                                                     float* __restrict__ out) {
    __shared__ __align__(16) float sbuf[SR_N][232];  // 4 zero | 224 | 4 zero
    unsigned g0  = blockIdx.x * CR;
    unsigned bc  = blockIdx.y;
    unsigned tid = threadIdx.x;
    unsigned w = tid >> 5, lane = tid & 31u;

    // zero the 8 pad floats of each staged row (27*8 = 216 threads)
    if (tid < SR_N * 8u) {
        unsigned sr = tid >> 3u, p = tid & 7u;
        sbuf[sr][p < 4u ? p : 224u + p] = 0.0f;
    }
    // vector staging: 27 rows x 56 float4 across 288 threads
    {
        const float4* xb4 = (const float4*)(x + (size_t)bc * ISTR);
        for (unsigned f = tid; f < SR_N * 56u; f += 288u) {
            unsigned sr = f / 56u;
            unsigned q  = f - 56u * sr;
            int ih = (int)g0 - 1 + (int)sr;
            float4 v = make_float4(0.f, 0.f, 0.f, 0.f);
            if ((unsigned)ih < 224u) v = __ldg(xb4 + (unsigned)ih * 56u + q);
            *((float4*)&sbuf[sr][4] + q) = v;
        }
    }
    __syncthreads();

    unsigned ki = w / 3u;
    unsigned kj = w - 3u * ki;
    unsigned ck = bc * 9u + w;
    unsigned nrows = (g0 + CR <= 223u) ? CR : (223u - g0);   // 24, last chunk 7

    for (unsigned r = 0; r < nrows; ++r) {
        unsigned oh   = g0 + r;
        size_t   drow = (size_t)ck * OSP + (size_t)oh * 223u;
        unsigned lead = (4u - ((unsigned)drow & 3u)) & 3u;
        unsigned tail = 3u - lead;
        unsigned sr   = r + ki;
        unsigned off  = lead + kj + 3u;     // padded-row idx of first body float
        unsigned dlt  = off & 3u;
        unsigned jb   = off >> 2u;
        const float4* sm4 = (const float4*)sbuf[sr];
        float4* dst4 = (float4*)(out + drow + lead);

        // 55 fully-in-row aligned float4 stores
        for (unsigned j = lane; j < 55u; j += 32u) {
            float4 a = sm4[jb + j];
            float4 b = sm4[jb + j + 1u];
            float4 v;
            switch (dlt) {
              case 0:  v = a; break;
              case 1:  v = make_float4(a.y, a.z, a.w, b.x); break;
              case 2:  v = make_float4(a.z, a.w, b.x, b.y); break;
              default: v = make_float4(a.w, b.x, b.y, b.z); break;
            }
            __stcs(dst4 + j, v);
        }

        // straddle float4 across row boundary (tail of oh + lead of oh+1)
        if (lane == 0u && tail != 0u && oh < 222u) {
            float vv[4];
#pragma unroll
            for (unsigned t = 0; t < 4u; ++t) {
                vv[t] = (t < tail) ? sbuf[sr][off + 220u + t]
                                   : sbuf[sr + 1u][(t - tail) + kj + 3u];
            }
            __stcs((float4*)(out + drow + lead + 220u),
                   make_float4(vv[0], vv[1], vv[2], vv[3]));
        }

        // plane-end tail scalars (oh == 222 only)
        if (oh == 222u && lane < tail) {
            __stcs(out + drow + lead + 220u + lane, sbuf[sr][off + 220u + lane]);
        }

        // plane-start head scalars (first chunk, first row only)
        if (g0 == 0u && r == 0u && lane < lead) {
            __stcs(out + drow + lane, sbuf[sr][lane + kj + 3u]);
        }
    }
}

extern "C" void kernel_launch(void* const* d_in, const int* in_sizes, int n_in,
                              void* d_out, int out_size) {
    const float* x = (const float*)d_in[0];
    float* out = (float*)d_out;
    dim3 grid(10, 256);   // 10 chunks (9*24 + 7 rows), 256 bc planes
    unfold_v13<<<grid, 288>>>(x, out);
}

// round 14
// speedup vs baseline: 1.0739x; 1.0739x over previous
#include <cuda_runtime.h>
#include <stdint.h>

// IN:  x (4, 64, 224, 224) fp32
// OUT: (4, 576, 223*223) fp32, plane ck = bc*9 + ki*3 + kj
// out[ck, oh*223+ow] = x[bc, oh+ki-1, ow+kj-1] (0 if OOB)
#define OSP    49729u     // 223*223
#define ISTR   50176u     // 224*224
#define ROWB   892u       // 223 * 4 bytes

// v10 structure + all-32-bit byte addressing + incremental per-row state:
// strips the 64-bit IMAD ladders that were eating 62% of issue (fma+alu).
__global__ void __launch_bounds__(288, 7) unfold_v14(const float* __restrict__ x,
                                                     float* __restrict__ out) {
    __shared__ __align__(16) float sbuf[11][232];  // 4 zero | 224 data | 4 zero
    unsigned g8  = blockIdx.x * 8u;
    unsigned bc  = blockIdx.y;
    unsigned tid = threadIdx.x;
    unsigned w = tid >> 5, lane = tid & 31u;

    // zero the 8 pad floats of each of the 11 rows
    if (tid < 88u) {
        unsigned sr = tid >> 3u, p = tid & 7u;
        sbuf[sr][p < 4u ? p : 224u + p] = 0.0f;
    }
    // vector staging: 11 rows x 56 float4 across all 288 threads
    {
        const float4* xb4 = (const float4*)(x + (size_t)bc * ISTR);
        for (unsigned f = tid; f < 616u; f += 288u) {
            unsigned sr = f / 56u;
            unsigned q  = f - 56u * sr;
            int ih = (int)g8 - 1 + (int)sr;
            float4 v = make_float4(0.f, 0.f, 0.f, 0.f);
            if ((unsigned)ih < 224u) v = __ldg(xb4 + (unsigned)ih * 56u + q);
            *((float4*)&sbuf[sr][4] + q) = v;
        }
    }
    __syncthreads();

    unsigned ki = w / 3u;
    unsigned kj = w - 3u * ki;
    unsigned ck = bc * 9u + w;
    unsigned nrows = (g8 + 8u <= 223u) ? 8u : (223u - g8);   // 8, last chunk 7
    unsigned kj3 = kj + 3u;

    // 32-bit byte offsets (total out = 458MB < 4GB)
    char* outc = (char*)out;
    unsigned orow = ck * (OSP * 4u) + g8 * ROWB;   // byte offset of row g8
    unsigned lead = (4u - ((orow >> 2) & 3u)) & 3u;
    const float* srow = sbuf[ki];                   // bumped +232 per r

    for (unsigned r = 0; r < nrows; ++r) {
        unsigned off = lead + kj3;          // padded-row idx of first body float
        unsigned dlt = off & 3u;
        unsigned jb  = off >> 2u;
        const float4* sm4 = (const float4*)srow;
        float4* dst4 = (float4*)(outc + orow + 4u * lead);

        // 55 fully-in-row aligned float4 stores
        for (unsigned j = lane; j < 55u; j += 32u) {
            float4 a = sm4[jb + j];
            float4 b = sm4[jb + j + 1u];
            float4 v;
            switch (dlt) {
              case 0:  v = a; break;
              case 1:  v = make_float4(a.y, a.z, a.w, b.x); break;
              case 2:  v = make_float4(a.z, a.w, b.x, b.y); break;
              default: v = make_float4(a.w, b.x, b.y, b.z); break;
            }
            __stcs(dst4 + j, v);
        }

        unsigned oh   = g8 + r;
        unsigned tail = 3u - lead;

        // straddle float4 across row boundary (tail of oh + lead of oh+1)
        if (lane == 0u && tail != 0u && oh < 222u) {
            float vv[4];
#pragma unroll
            for (unsigned t = 0; t < 4u; ++t) {
                vv[t] = (t < tail) ? srow[off + 220u + t]
                                   : srow[232u + (t - tail) + kj3];
            }
            __stcs((float4*)(outc + orow + 4u * lead + 880u),
                   make_float4(vv[0], vv[1], vv[2], vv[3]));
        }

        // plane-end tail scalars (oh == 222 only)
        if (oh == 222u && lane < tail) {
            __stcs((float*)(outc + orow + 4u * (lead + 220u + lane)),
                   srow[off + 220u + lane]);
        }

        // plane-start head scalars (first chunk, first row only)
        if (g8 == 0u && r == 0u && lane < lead) {
            __stcs((float*)(outc + orow + 4u * lane), srow[lane + kj3]);
        }

        orow += ROWB;
        lead = (lead + 1u) & 3u;            // 223 % 4 == 3 => lead cycles +1
        srow += 232u;
    }
}

extern "C" void kernel_launch(void* const* d_in, const int* in_sizes, int n_in,
                              void* d_out, int out_size) {
    const float* x = (const float*)d_in[0];
    float* out = (float*)d_out;
    dim3 grid(28, 256);   // 28 row-groups (27*8 + 7), 256 bc planes
    unfold_v14<<<grid, 288>>>(x, out);
}